// round 9
// baseline (speedup 1.0000x reference)
#include <cuda_runtime.h>
#include <math.h>

#define BATCH   64
#define T_IN    104
#define NFEAT   20
#define NPEMB   64
#define NCOND   256
#define NSUB    40
#define NSTEPS  400
#define NBF     100

// ---------------- scratch (__device__ globals; no runtime allocation) ----------------
static __device__ float g_t   [BATCH * T_IN * NCOND];   // fd1 output (B, 104, 256)
static __device__ float g_c1  [BATCH * 102  * NCOND];   // conv1 output (B, 102, 256)
static __device__ float g_c2  [BATCH * NBF  * NCOND];   // conv2 output (B, 100, 256)
static __device__ float g_cond[BATCH * NBF  * NCOND];   // fd2 output (B, 100, 256)
static __device__ float g_pre [BATCH * NSTEPS * NSUB];  // phase cos (B, 400, 40)
static __device__ float g_pim [BATCH * NSTEPS * NSUB];  // phase sin
static __device__ float g_w1t [NCOND * 3 * NCOND];      // conv1_w -> (i*3+d, o)
static __device__ float g_w2t [NCOND * 3 * NCOND];      // conv2_w -> (i*3+d, o)

__device__ __forceinline__ float sigm(float x) { return 1.0f / (1.0f + expf(-x)); }

// ---------------- phase embedding ----------------
// Replicate reference fp32 cumsum exactly; evaluate sin/cos of the f32 phase in double.
__global__ void phase_kernel(const int* __restrict__ period,
                             const float* __restrict__ rshift) {
    const float TWOPI = 6.28318530717958647692f;
    int b = blockIdx.x;
    __shared__ float s_cum[NBF], s_w0[NBF];
    if (threadIdx.x == 0) {
        float acc = TWOPI * rshift[b] / 160.0f;   // w0_shift[0]
        for (int f = 0; f < NBF; f++) {
            float w0 = TWOPI / (float)period[b * T_IN + 3 + f];
            s_w0[f]  = w0;
            s_cum[f] = 160.0f * acc;              // FRAME * cumsum(w0_shift)[f]
            acc += w0;                            // w0_shift[f+1] = w0[f]
        }
    }
    __syncthreads();
    float* pre = g_pre + (size_t)b * NSTEPS * NSUB;
    float* pim = g_pim + (size_t)b * NSTEPS * NSUB;
    for (int idx = threadIdx.x; idx < NSTEPS * NSUB; idx += blockDim.x) {
        int s = idx / NSUB, j = idx - s * NSUB;
        int f = s >> 2, q = s & 3;
        float e = s_cum[f] + s_w0[f] * (float)(q * NSUB + j);  // fp32, matches ref
        double sv, cv;
        sincos((double)e, &sv, &cv);
        pre[idx] = (float)cv;
        pim[idx] = (float)sv;
    }
}

// ---------------- conv weight transpose: (O, I, 3) -> (I*3+d, O) ----------------
__global__ void wtrans_kernel(const float* __restrict__ w1, const float* __restrict__ w2) {
    int idx = blockIdx.x * 256 + threadIdx.x;
    if (idx < NCOND * NCOND * 3) {
        int o = idx / (NCOND * 3);
        int r = idx - o * (NCOND * 3);      // i*3 + d
        g_w1t[r * NCOND + o] = w1[idx];
        g_w2t[r * NCOND + o] = w2[idx];
    }
}

// ---------------- fd1: tanh([features | pembed[period]] @ (84,256) + b) ----------------
__global__ void fd1_kernel(const float* __restrict__ feat, const int* __restrict__ period,
                           const float* __restrict__ pemb, const float* __restrict__ w,
                           const float* __restrict__ bias) {
    int bt  = blockIdx.x;                   // b*T_IN + tau
    int tid = threadIdx.x;
    __shared__ float xs[NFEAT + NPEMB];
    if (tid < NFEAT)                 xs[tid] = feat[(size_t)bt * NFEAT + tid];
    else if (tid < NFEAT + NPEMB)    xs[tid] = pemb[(size_t)period[bt] * NPEMB + (tid - NFEAT)];
    __syncthreads();
    float acc = bias[tid];
#pragma unroll 4
    for (int k = 0; k < NFEAT + NPEMB; k++)
        acc = fmaf(xs[k], w[(size_t)k * NCOND + tid], acc);
    g_t[(size_t)bt * NCOND + tid] = tanhf(acc);
}

// ---------------- valid conv k=3 (768->256 matvec per position), tanh -----------------
__global__ void conv_kernel(const float* __restrict__ bias, int stage) {
    int t_in  = stage ? 102 : 104;
    int t_out = t_in - 2;
    int b   = blockIdx.x / t_out;
    int tau = blockIdx.x - b * t_out;
    const float* xin  = stage ? g_c1  : g_t;
    float*       yout = stage ? g_c2  : g_c1;
    const float* wt   = stage ? g_w2t : g_w1t;
    __shared__ float  xs[768];
    __shared__ float4 part[256];
    int tid = threadIdx.x;
    for (int e = tid; e < 768; e += 256) {
        int i = e / 3, d = e - 3 * i;
        xs[e] = xin[((size_t)(b * t_in + tau + d)) * NCOND + i];
    }
    __syncthreads();
    int g = tid & 63, ks = tid >> 6;        // 64 output groups x 4 K-splits
    const float* Wp = wt + 4 * g;
    float4 acc = make_float4(0.f, 0.f, 0.f, 0.f);
    int k0 = ks * 192;
#pragma unroll 4
    for (int k = k0; k < k0 + 192; k++) {
        float  xk = xs[k];
        float4 w  = *(const float4*)(Wp + (size_t)k * NCOND);
        acc.x = fmaf(w.x, xk, acc.x); acc.y = fmaf(w.y, xk, acc.y);
        acc.z = fmaf(w.z, xk, acc.z); acc.w = fmaf(w.w, xk, acc.w);
    }
    part[tid] = acc;
    __syncthreads();
    if (tid < 64) {
        float4 r = part[tid];
#pragma unroll
        for (int u = 1; u < 4; u++) {
            float4 p = part[u * 64 + tid];
            r.x += p.x; r.y += p.y; r.z += p.z; r.w += p.w;
        }
        float4 bb = *(const float4*)(bias + 4 * tid);
        float* yp = yout + (size_t)blockIdx.x * NCOND + 4 * tid;
        yp[0] = tanhf(r.x + bb.x); yp[1] = tanhf(r.y + bb.y);
        yp[2] = tanhf(r.z + bb.z); yp[3] = tanhf(r.w + bb.w);
    }
}

// ---------------- fd2: tanh(conv2_out @ (256,256) + b) ----------------
__global__ void fd2_kernel(const float* __restrict__ w, const float* __restrict__ bias) {
    int bf  = blockIdx.x;                   // b*100 + f
    int tid = threadIdx.x;
    __shared__ float  xs[NCOND];
    __shared__ float4 part[256];
    xs[tid] = g_c2[(size_t)bf * NCOND + tid];
    __syncthreads();
    int g = tid & 63, ks = tid >> 6;
    const float* Wp = w + 4 * g;
    float4 acc = make_float4(0.f, 0.f, 0.f, 0.f);
    int k0 = ks * 64;
#pragma unroll 4
    for (int k = k0; k < k0 + 64; k++) {
        float  xk = xs[k];
        float4 wv = *(const float4*)(Wp + (size_t)k * NCOND);
        acc.x = fmaf(wv.x, xk, acc.x); acc.y = fmaf(wv.y, xk, acc.y);
        acc.z = fmaf(wv.z, xk, acc.z); acc.w = fmaf(wv.w, xk, acc.w);
    }
    part[tid] = acc;
    __syncthreads();
    if (tid < 64) {
        float4 r = part[tid];
#pragma unroll
        for (int u = 1; u < 4; u++) {
            float4 p = part[u * 64 + tid];
            r.x += p.x; r.y += p.y; r.z += p.z; r.w += p.w;
        }
        float4 bb = *(const float4*)(bias + 4 * tid);
        float* yp = g_cond + (size_t)bf * NCOND + 4 * tid;
        yp[0] = tanhf(r.x + bb.x); yp[1] = tanhf(r.y + bb.y);
        yp[2] = tanhf(r.z + bb.z); yp[3] = tanhf(r.w + bb.w);
    }
}

// ---------------- recurrence helpers (384 threads) ----------------
// y = tanh(x @ W(K,256) + b): 64 groups x 4 outputs, 6 K-splits, smem reduce.
__device__ __forceinline__ void mv256(const float* __restrict__ W, const float* __restrict__ bias,
                                      const float* x, float* y, int K, float4* part, int tid) {
    int g = tid & 63, ks = tid >> 6;
    int kper = (K + 5) / 6;
    int k0 = ks * kper;
    int k1 = k0 + kper; if (k1 > K) k1 = K;
    const float* Wp = W + 4 * g;
    float4 acc = make_float4(0.f, 0.f, 0.f, 0.f);
#pragma unroll 4
    for (int k = k0; k < k1; k++) {
        float  xk = x[k];
        float4 w  = *(const float4*)(Wp + (size_t)k * NCOND);
        acc.x = fmaf(w.x, xk, acc.x); acc.y = fmaf(w.y, xk, acc.y);
        acc.z = fmaf(w.z, xk, acc.z); acc.w = fmaf(w.w, xk, acc.w);
    }
    part[tid] = acc;
    __syncthreads();
    if (tid < 64) {
        float4 r = part[tid];
#pragma unroll
        for (int u = 1; u < 6; u++) {
            float4 p = part[u * 64 + tid];
            r.x += p.x; r.y += p.y; r.z += p.z; r.w += p.w;
        }
        float4 bb = *(const float4*)(bias + 4 * tid);
        y[4 * tid + 0] = tanhf(r.x + bb.x);
        y[4 * tid + 1] = tanhf(r.y + bb.y);
        y[4 * tid + 2] = tanhf(r.z + bb.z);
        y[4 * tid + 3] = tanhf(r.w + bb.w);
    }
    __syncthreads();
}

// GRU gates: threads 0..191 compute gi = x@wi+bi (768), 192..383 compute gh = h@wh+bh.
__device__ __forceinline__ void gru_gates(const float* __restrict__ wi, const float* __restrict__ bi,
                                          const float* __restrict__ wh, const float* __restrict__ bh,
                                          const float* x, const float* h,
                                          float* gi, float* gh, int tid) {
    int half = (tid >= 192);
    int g = tid - half * 192;
    const float* W = half ? wh : wi;
    const float* B = half ? bh : bi;
    const float* v = half ? h  : x;
    float*     dst = half ? gh : gi;
    const float* Wp = W + 4 * g;
    float4 acc = *(const float4*)(B + 4 * g);
#pragma unroll 4
    for (int k = 0; k < NCOND; k++) {
        float  xk = v[k];
        float4 w  = *(const float4*)(Wp + (size_t)k * 768);
        acc.x = fmaf(w.x, xk, acc.x); acc.y = fmaf(w.y, xk, acc.y);
        acc.z = fmaf(w.z, xk, acc.z); acc.w = fmaf(w.w, xk, acc.w);
    }
    ((float4*)dst)[g] = acc;
    __syncthreads();
}

__device__ __forceinline__ void gru_combine(const float* gi, const float* gh, float* h, int tid) {
    if (tid < NCOND) {
        float r = sigm(gi[tid] + gh[tid]);
        float z = sigm(gi[NCOND + tid] + gh[NCOND + tid]);
        float n = tanhf(fmaf(r, gh[2 * NCOND + tid], gi[2 * NCOND + tid]));
        h[tid] = fmaf(z, h[tid] - n, n);    // (1-z)*n + z*h
    }
    __syncthreads();
}

// ---------------- autoregressive recurrence: 1 CTA per batch element ----------------
__global__ void __launch_bounds__(384) rnn_kernel(
    const float* __restrict__ sd1_w, const float* __restrict__ sd1_b,
    const float* __restrict__ sd2_w, const float* __restrict__ sd2_b,
    const float* __restrict__ g1_wi, const float* __restrict__ g1_bi,
    const float* __restrict__ g1_wh, const float* __restrict__ g1_bh,
    const float* __restrict__ g2_wi, const float* __restrict__ g2_bi,
    const float* __restrict__ g2_wh, const float* __restrict__ g2_bh,
    const float* __restrict__ g3_wi, const float* __restrict__ g3_bi,
    const float* __restrict__ g3_wh, const float* __restrict__ g3_bh,
    const float* __restrict__ out_w, const float* __restrict__ out_b,
    float* __restrict__ d_sig, float* __restrict__ d_h, int write_h)
{
    int b = blockIdx.x, tid = threadIdx.x;
    __shared__ float  x_in[384];            // [cond 0:256 | prev 256:296 | pr 296:336 | pi 336:376]
    __shared__ float  tt[NCOND];
    __shared__ float  gi[768], gh[768];
    __shared__ float  h1[NCOND], h2[NCOND], h3[NCOND];
    __shared__ float4 part[384];

    if (tid < NCOND) { h1[tid] = 0.f; h2[tid] = 0.f; h3[tid] = 0.f; }
    if (tid >= 256 && tid < 296) x_in[tid] = 0.f;   // prev = 0
    __syncthreads();

    const float* pre = g_pre  + (size_t)b * NSTEPS * NSUB;
    const float* pim = g_pim  + (size_t)b * NSTEPS * NSUB;
    const float* cnd = g_cond + (size_t)b * NBF * NCOND;
    float*       sig = d_sig  + (size_t)b * NSTEPS * NSUB;

    for (int s = 0; s < NSTEPS; s++) {
        if (tid < 256)                       x_in[tid] = cnd[(size_t)(s >> 2) * NCOND + tid];
        else if (tid >= 296 && tid < 336)    x_in[tid] = pre[s * NSUB + (tid - 296)];
        else if (tid >= 336 && tid < 376)    x_in[tid] = pim[s * NSUB + (tid - 336)];
        __syncthreads();

        mv256(sd1_w, sd1_b, x_in, tt, 376, part, tid);         // sd1 + tanh
        mv256(sd2_w, sd2_b, tt,   tt, 256, part, tid);         // sd2 + tanh

        gru_gates(g1_wi, g1_bi, g1_wh, g1_bh, tt, h1, gi, gh, tid);
        gru_combine(gi, gh, h1, tid);
        gru_gates(g2_wi, g2_bi, g2_wh, g2_bh, h1, h2, gi, gh, tid);
        gru_combine(gi, gh, h2, tid);
        gru_gates(g3_wi, g3_bi, g3_wh, g3_bh, h2, h3, gi, gh, tid);
        gru_combine(gi, gh, h3, tid);

        // out layer: 256 -> 40; 10 groups x 32 K-splits (8 k each)
        if (tid < 320) {
            int g = tid % 10, ks = tid / 10;
            const float* Wp = out_w + 4 * g;
            float4 acc = make_float4(0.f, 0.f, 0.f, 0.f);
            int k0 = ks * 8;
#pragma unroll
            for (int k = k0; k < k0 + 8; k++) {
                float  xk = h3[k];
                float4 w  = *(const float4*)(Wp + (size_t)k * NSUB);
                acc.x = fmaf(w.x, xk, acc.x); acc.y = fmaf(w.y, xk, acc.y);
                acc.z = fmaf(w.z, xk, acc.z); acc.w = fmaf(w.w, xk, acc.w);
            }
            part[tid] = acc;
        }
        __syncthreads();
        if (tid < 10) {
            float4 r = part[tid];
#pragma unroll
            for (int u = 1; u < 32; u++) {
                float4 p = part[u * 10 + tid];
                r.x += p.x; r.y += p.y; r.z += p.z; r.w += p.w;
            }
            float4 bb = *(const float4*)(out_b + 4 * tid);
            float v0 = tanhf(r.x + bb.x), v1 = tanhf(r.y + bb.y);
            float v2 = tanhf(r.z + bb.z), v3 = tanhf(r.w + bb.w);
            float* sp = sig + (size_t)s * NSUB + 4 * tid;
            sp[0] = v0; sp[1] = v1; sp[2] = v2; sp[3] = v3;
            x_in[256 + 4 * tid + 0] = v0;   // prev for next step
            x_in[256 + 4 * tid + 1] = v1;
            x_in[256 + 4 * tid + 2] = v2;
            x_in[256 + 4 * tid + 3] = v3;
        }
        __syncthreads();
    }

    if (write_h && tid < NCOND) {
        d_h[(size_t)b * NCOND + tid]               = h1[tid];
        d_h[(size_t)(BATCH + b) * NCOND + tid]     = h2[tid];
        d_h[(size_t)(2 * BATCH + b) * NCOND + tid] = h3[tid];
    }
}

// ---------------- launch ----------------
extern "C" void kernel_launch(void* const* d_in, const int* in_sizes, int n_in,
                              void* d_out, int out_size) {
    (void)n_in; (void)in_sizes;
    const float* features = (const float*)d_in[0];
    const int*   period   = (const int*)  d_in[1];
    // d_in[2] = nb_frames (scalar, fixed at 100)
    const float* rshift   = (const float*)d_in[3];
    const float* pembed   = (const float*)d_in[4];
    const float* fd1_w = (const float*)d_in[5],  *fd1_b = (const float*)d_in[6];
    const float* c1_w  = (const float*)d_in[7],  *c1_b  = (const float*)d_in[8];
    const float* c2_w  = (const float*)d_in[9],  *c2_b  = (const float*)d_in[10];
    const float* fd2_w = (const float*)d_in[11], *fd2_b = (const float*)d_in[12];
    const float* sd1_w = (const float*)d_in[13], *sd1_b = (const float*)d_in[14];
    const float* sd2_w = (const float*)d_in[15], *sd2_b = (const float*)d_in[16];
    const float* g1_wi = (const float*)d_in[17], *g1_bi = (const float*)d_in[18];
    const float* g1_wh = (const float*)d_in[19], *g1_bh = (const float*)d_in[20];
    const float* g2_wi = (const float*)d_in[21], *g2_bi = (const float*)d_in[22];
    const float* g2_wh = (const float*)d_in[23], *g2_bh = (const float*)d_in[24];
    const float* g3_wi = (const float*)d_in[25], *g3_bi = (const float*)d_in[26];
    const float* g3_wh = (const float*)d_in[27], *g3_bh = (const float*)d_in[28];
    const float* out_w = (const float*)d_in[29], *out_b = (const float*)d_in[30];

    float* d_sig = (float*)d_out;
    const int sig_elems = BATCH * NSTEPS * NSUB;             // 1,024,000
    int write_h = (out_size >= sig_elems + 3 * BATCH * NCOND) ? 1 : 0;
    float* d_h = d_sig + sig_elems;

    // Conditioning network (parallel over B*T)
    wtrans_kernel<<<(NCOND * NCOND * 3 + 255) / 256, 256>>>(c1_w, c2_w);
    phase_kernel<<<BATCH, 256>>>(period, rshift);
    fd1_kernel<<<BATCH * T_IN, 256>>>(features, period, pembed, fd1_w, fd1_b);
    conv_kernel<<<BATCH * 102, 256>>>(c1_b, 0);
    conv_kernel<<<BATCH * 100, 256>>>(c2_b, 1);
    fd2_kernel<<<BATCH * NBF, 256>>>(fd2_w, fd2_b);

    // Autoregressive recurrence: 64 persistent CTAs
    rnn_kernel<<<BATCH, 384>>>(sd1_w, sd1_b, sd2_w, sd2_b,
                               g1_wi, g1_bi, g1_wh, g1_bh,
                               g2_wi, g2_bi, g2_wh, g2_bh,
                               g3_wi, g3_bi, g3_wh, g3_bh,
                               out_w, out_b, d_sig, d_h, write_h);
}

// round 10
// speedup vs baseline: 3.2175x; 3.2175x over previous
#include <cuda_runtime.h>
#include <cooperative_groups.h>
#include <math.h>

namespace cg = cooperative_groups;

#define BATCH   64
#define T_IN    104
#define NFEAT   20
#define NPEMB   64
#define NCOND   256
#define NSUB    40
#define NSTEPS  400
#define NBF     100

// ---------------- scratch (__device__ globals; no runtime allocation) ----------------
static __device__ float g_t   [BATCH * T_IN * NCOND];
static __device__ float g_c1  [BATCH * 102  * NCOND];
static __device__ float g_c2  [BATCH * NBF  * NCOND];
static __device__ float g_cond[BATCH * NBF  * NCOND];
static __device__ float g_pre [BATCH * NSTEPS * NSUB];
static __device__ float g_pim [BATCH * NSTEPS * NSUB];
static __device__ float g_w1t [NCOND * 3 * NCOND];
static __device__ float g_w2t [NCOND * 3 * NCOND];

__device__ __forceinline__ float sigm(float x) { return 1.0f / (1.0f + expf(-x)); }
__device__ __forceinline__ void f4add(float4& a, const float4& b) {
    a.x += b.x; a.y += b.y; a.z += b.z; a.w += b.w;
}

// ---------------- phase embedding (unchanged from R8 — passed) ----------------
__global__ void phase_kernel(const int* __restrict__ period,
                             const float* __restrict__ rshift) {
    const float TWOPI = 6.28318530717958647692f;
    int b = blockIdx.x;
    __shared__ float s_cum[NBF], s_w0[NBF];
    if (threadIdx.x == 0) {
        float acc = TWOPI * rshift[b] / 160.0f;
        for (int f = 0; f < NBF; f++) {
            float w0 = TWOPI / (float)period[b * T_IN + 3 + f];
            s_w0[f]  = w0;
            s_cum[f] = 160.0f * acc;
            acc += w0;
        }
    }
    __syncthreads();
    float* pre = g_pre + (size_t)b * NSTEPS * NSUB;
    float* pim = g_pim + (size_t)b * NSTEPS * NSUB;
    for (int idx = threadIdx.x; idx < NSTEPS * NSUB; idx += blockDim.x) {
        int s = idx / NSUB, j = idx - s * NSUB;
        int f = s >> 2, q = s & 3;
        float e = s_cum[f] + s_w0[f] * (float)(q * NSUB + j);
        double sv, cv;
        sincos((double)e, &sv, &cv);
        pre[idx] = (float)cv;
        pim[idx] = (float)sv;
    }
}

__global__ void wtrans_kernel(const float* __restrict__ w1, const float* __restrict__ w2) {
    int idx = blockIdx.x * 256 + threadIdx.x;
    if (idx < NCOND * NCOND * 3) {
        int o = idx / (NCOND * 3);
        int r = idx - o * (NCOND * 3);
        g_w1t[r * NCOND + o] = w1[idx];
        g_w2t[r * NCOND + o] = w2[idx];
    }
}

__global__ void fd1_kernel(const float* __restrict__ feat, const int* __restrict__ period,
                           const float* __restrict__ pemb, const float* __restrict__ w,
                           const float* __restrict__ bias) {
    int bt  = blockIdx.x;
    int tid = threadIdx.x;
    __shared__ float xs[NFEAT + NPEMB];
    if (tid < NFEAT)                 xs[tid] = feat[(size_t)bt * NFEAT + tid];
    else if (tid < NFEAT + NPEMB)    xs[tid] = pemb[(size_t)period[bt] * NPEMB + (tid - NFEAT)];
    __syncthreads();
    float acc = bias[tid];
#pragma unroll 4
    for (int k = 0; k < NFEAT + NPEMB; k++)
        acc = fmaf(xs[k], w[(size_t)k * NCOND + tid], acc);
    g_t[(size_t)bt * NCOND + tid] = tanhf(acc);
}

__global__ void conv_kernel(const float* __restrict__ bias, int stage) {
    int t_in  = stage ? 102 : 104;
    int t_out = t_in - 2;
    int b   = blockIdx.x / t_out;
    int tau = blockIdx.x - b * t_out;
    const float* xin  = stage ? g_c1  : g_t;
    float*       yout = stage ? g_c2  : g_c1;
    const float* wt   = stage ? g_w2t : g_w1t;
    __shared__ float  xs[768];
    __shared__ float4 part[256];
    int tid = threadIdx.x;
    for (int e = tid; e < 768; e += 256) {
        int i = e / 3, d = e - 3 * i;
        xs[e] = xin[((size_t)(b * t_in + tau + d)) * NCOND + i];
    }
    __syncthreads();
    int g = tid & 63, ks = tid >> 6;
    const float* Wp = wt + 4 * g;
    float4 acc = make_float4(0.f, 0.f, 0.f, 0.f);
    int k0 = ks * 192;
#pragma unroll 4
    for (int k = k0; k < k0 + 192; k++) {
        float  xk = xs[k];
        float4 w  = *(const float4*)(Wp + (size_t)k * NCOND);
        acc.x = fmaf(w.x, xk, acc.x); acc.y = fmaf(w.y, xk, acc.y);
        acc.z = fmaf(w.z, xk, acc.z); acc.w = fmaf(w.w, xk, acc.w);
    }
    part[tid] = acc;
    __syncthreads();
    if (tid < 64) {
        float4 r = part[tid];
#pragma unroll
        for (int u = 1; u < 4; u++) f4add(r, part[u * 64 + tid]);
        float4 bb = *(const float4*)(bias + 4 * tid);
        float* yp = yout + (size_t)blockIdx.x * NCOND + 4 * tid;
        yp[0] = tanhf(r.x + bb.x); yp[1] = tanhf(r.y + bb.y);
        yp[2] = tanhf(r.z + bb.z); yp[3] = tanhf(r.w + bb.w);
    }
}

__global__ void fd2_kernel(const float* __restrict__ w, const float* __restrict__ bias) {
    int bf  = blockIdx.x;
    int tid = threadIdx.x;
    __shared__ float  xs[NCOND];
    __shared__ float4 part[256];
    xs[tid] = g_c2[(size_t)bf * NCOND + tid];
    __syncthreads();
    int g = tid & 63, ks = tid >> 6;
    const float* Wp = w + 4 * g;
    float4 acc = make_float4(0.f, 0.f, 0.f, 0.f);
    int k0 = ks * 64;
#pragma unroll 4
    for (int k = k0; k < k0 + 64; k++) {
        float  xk = xs[k];
        float4 wv = *(const float4*)(Wp + (size_t)k * NCOND);
        acc.x = fmaf(wv.x, xk, acc.x); acc.y = fmaf(wv.y, xk, acc.y);
        acc.z = fmaf(wv.z, xk, acc.z); acc.w = fmaf(wv.w, xk, acc.w);
    }
    part[tid] = acc;
    __syncthreads();
    if (tid < 64) {
        float4 r = part[tid];
#pragma unroll
        for (int u = 1; u < 4; u++) f4add(r, part[u * 64 + tid]);
        float4 bb = *(const float4*)(bias + 4 * tid);
        float* yp = g_cond + (size_t)bf * NCOND + 4 * tid;
        yp[0] = tanhf(r.x + bb.x); yp[1] = tanhf(r.y + bb.y);
        yp[2] = tanhf(r.z + bb.z); yp[3] = tanhf(r.w + bb.w);
    }
}

// ======================= cluster-2 recurrence =======================
// Cluster of 2 CTAs per batch element. CTA rank r computes output
// columns [128r, 128r+128) of every 256-wide layer (and [20r, 20r+20)
// of the out layer). Activations are full per-CTA; each CTA writes its
// computed half to its own smem AND the peer's via DSMEM, then
// cluster.sync(). Hidden states are double-buffered by step parity so a
// combine-write never races the peer's same-phase gate-matvec read.

// GRU layer: gates matvec (768 threads: 192 float4-groups x 4 K-splits),
// reduce+bias, combine, exchange new h half.
__device__ __forceinline__ void gru_layer(
    const float* __restrict__ wi, const float* __restrict__ bi,
    const float* __restrict__ wh, const float* __restrict__ bh,
    const float* xv, const float* h_old, float* h_new, float* p_h_new,
    float* gil, float* ghl, float4* part, int rank, int tid,
    cg::cluster_group& cluster)
{
    {
        int g = tid % 192, ks = tid / 192;          // warps 0-2 of each 192: gi; 3-5: gh
        int gg = g;
        const float* W; const float* v;
        if (g < 96) { W = wi; v = xv; }
        else        { W = wh; v = h_old; gg = g - 96; }
        int t  = gg >> 5;
        const float* Wp = W + 256 * t + 128 * rank + 4 * (gg & 31);
        float4 a = make_float4(0.f, 0.f, 0.f, 0.f);
        int k0 = ks * 64;
#pragma unroll 8
        for (int k = k0; k < k0 + 64; k++) {
            float  xk = v[k];
            float4 w  = *(const float4*)(Wp + (size_t)k * 768);
            a.x = fmaf(w.x, xk, a.x); a.y = fmaf(w.y, xk, a.y);
            a.z = fmaf(w.z, xk, a.z); a.w = fmaf(w.w, xk, a.w);
        }
        part[tid] = a;
    }
    __syncthreads();
    if (tid < 192) {
        int g = tid;
        float4 r = part[g];
#pragma unroll
        for (int u = 1; u < 4; u++) f4add(r, part[u * 192 + g]);
        int gg = (g < 96) ? g : g - 96;
        int t  = gg >> 5;
        int jl = 4 * (gg & 31);
        const float* B = (g < 96) ? bi : bh;
        float4 bb = *(const float4*)(B + 256 * t + 128 * rank + jl);
        r.x += bb.x; r.y += bb.y; r.z += bb.z; r.w += bb.w;
        float* dst = (g < 96) ? gil : ghl;
        *(float4*)(dst + t * 128 + jl) = r;
    }
    __syncthreads();
    if (tid < 128) {
        int c = 128 * rank + tid;
        float rg = sigm(gil[tid]       + ghl[tid]);
        float zg = sigm(gil[128 + tid] + ghl[128 + tid]);
        float ng = tanhf(fmaf(rg, ghl[256 + tid], gil[256 + tid]));
        float hv = fmaf(zg, h_old[c] - ng, ng);     // (1-z)*n + z*h
        h_new[c]   = hv;
        p_h_new[c] = hv;
    }
    cluster.sync();
}

__global__ void __cluster_dims__(2, 1, 1) __launch_bounds__(768, 1) rnn_kernel(
    const float* __restrict__ sd1_w, const float* __restrict__ sd1_b,
    const float* __restrict__ sd2_w, const float* __restrict__ sd2_b,
    const float* __restrict__ g1_wi, const float* __restrict__ g1_bi,
    const float* __restrict__ g1_wh, const float* __restrict__ g1_bh,
    const float* __restrict__ g2_wi, const float* __restrict__ g2_bi,
    const float* __restrict__ g2_wh, const float* __restrict__ g2_bh,
    const float* __restrict__ g3_wi, const float* __restrict__ g3_bi,
    const float* __restrict__ g3_wh, const float* __restrict__ g3_bh,
    const float* __restrict__ out_w, const float* __restrict__ out_b,
    float* __restrict__ d_sig, float* __restrict__ d_h, int write_h)
{
    cg::cluster_group cluster = cg::this_cluster();
    const int rank = (int)cluster.block_rank();
    const int peer = rank ^ 1;
    const int b    = blockIdx.x >> 1;
    const int tid  = threadIdx.x;

    __shared__ float  x_in[384];        // [cond 0:256 | prev 256:296 | pr 296:336 | pi 336:376]
    __shared__ float  tt[NCOND], tt2[NCOND];
    __shared__ float  hbuf[3][2][NCOND];
    __shared__ float  gil[384], ghl[384];
    __shared__ float4 part[768];
    __shared__ float4 red2[40];

    float* p_xin = cluster.map_shared_rank(x_in, peer);
    float* p_tt  = cluster.map_shared_rank(tt,   peer);
    float* p_tt2 = cluster.map_shared_rank(tt2,  peer);
    float* p_hb  = cluster.map_shared_rank(&hbuf[0][0][0], peer);

    if (tid < NCOND) {
#pragma unroll
        for (int l = 0; l < 3; l++) { hbuf[l][0][tid] = 0.f; hbuf[l][1][tid] = 0.f; }
    }
    if (tid >= 256 && tid < 296) x_in[tid] = 0.f;   // prev = 0
    cluster.sync();                                  // init visible cluster-wide

    const float* pre = g_pre  + (size_t)b * NSTEPS * NSUB;
    const float* pim = g_pim  + (size_t)b * NSTEPS * NSUB;
    const float* cnd = g_cond + (size_t)b * NBF * NCOND;
    float*       sig = d_sig  + (size_t)b * NSTEPS * NSUB;

    for (int s = 0; s < NSTEPS; s++) {
        const int p = s & 1;
        if (tid < 256)                       x_in[tid] = cnd[(size_t)(s >> 2) * NCOND + tid];
        else if (tid >= 296 && tid < 336)    x_in[tid] = pre[s * NSUB + (tid - 296)];
        else if (tid >= 336 && tid < 376)    x_in[tid] = pim[s * NSUB + (tid - 336)];
        __syncthreads();

        // ---- sd1: 376 -> 256, this CTA's 128 outputs; 32 groups x 24 K-splits
        {
            int g = tid & 31, ks = tid >> 5;
            int k0 = ks * 16, k1 = k0 + 16; if (k1 > 376) k1 = 376;
            const float* Wp = sd1_w + 128 * rank + 4 * g;
            float4 a = make_float4(0.f, 0.f, 0.f, 0.f);
#pragma unroll 8
            for (int k = k0; k < k1; k++) {
                float  xk = x_in[k];
                float4 w  = *(const float4*)(Wp + (size_t)k * NCOND);
                a.x = fmaf(w.x, xk, a.x); a.y = fmaf(w.y, xk, a.y);
                a.z = fmaf(w.z, xk, a.z); a.w = fmaf(w.w, xk, a.w);
            }
            part[tid] = a;
            __syncthreads();
            if (tid < 32) {
                float4 r = part[tid];
#pragma unroll
                for (int u = 1; u < 24; u++) f4add(r, part[u * 32 + tid]);
                float4 bb = *(const float4*)(sd1_b + 128 * rank + 4 * tid);
                int c = 128 * rank + 4 * tid;
                float v0 = tanhf(r.x + bb.x), v1 = tanhf(r.y + bb.y);
                float v2 = tanhf(r.z + bb.z), v3 = tanhf(r.w + bb.w);
                tt[c] = v0; tt[c + 1] = v1; tt[c + 2] = v2; tt[c + 3] = v3;
                p_tt[c] = v0; p_tt[c + 1] = v1; p_tt[c + 2] = v2; p_tt[c + 3] = v3;
            }
            cluster.sync();
        }

        // ---- sd2: 256 -> 256
        {
            int g = tid & 31, ks = tid >> 5;
            int k0 = ks * 11, k1 = k0 + 11; if (k1 > 256) k1 = 256;
            const float* Wp = sd2_w + 128 * rank + 4 * g;
            float4 a = make_float4(0.f, 0.f, 0.f, 0.f);
#pragma unroll 8
            for (int k = k0; k < k1; k++) {
                float  xk = tt[k];
                float4 w  = *(const float4*)(Wp + (size_t)k * NCOND);
                a.x = fmaf(w.x, xk, a.x); a.y = fmaf(w.y, xk, a.y);
                a.z = fmaf(w.z, xk, a.z); a.w = fmaf(w.w, xk, a.w);
            }
            part[tid] = a;
            __syncthreads();
            if (tid < 32) {
                float4 r = part[tid];
#pragma unroll
                for (int u = 1; u < 24; u++) f4add(r, part[u * 32 + tid]);
                float4 bb = *(const float4*)(sd2_b + 128 * rank + 4 * tid);
                int c = 128 * rank + 4 * tid;
                float v0 = tanhf(r.x + bb.x), v1 = tanhf(r.y + bb.y);
                float v2 = tanhf(r.z + bb.z), v3 = tanhf(r.w + bb.w);
                tt2[c] = v0; tt2[c + 1] = v1; tt2[c + 2] = v2; tt2[c + 3] = v3;
                p_tt2[c] = v0; p_tt2[c + 1] = v1; p_tt2[c + 2] = v2; p_tt2[c + 3] = v3;
            }
            cluster.sync();
        }

        // ---- three GRUs (double-buffered hidden states)
        gru_layer(g1_wi, g1_bi, g1_wh, g1_bh, tt2, &hbuf[0][p][0], &hbuf[0][p ^ 1][0],
                  p_hb + (0 * 2 + (p ^ 1)) * NCOND, gil, ghl, part, rank, tid, cluster);
        gru_layer(g2_wi, g2_bi, g2_wh, g2_bh, &hbuf[0][p ^ 1][0], &hbuf[1][p][0], &hbuf[1][p ^ 1][0],
                  p_hb + (1 * 2 + (p ^ 1)) * NCOND, gil, ghl, part, rank, tid, cluster);
        gru_layer(g3_wi, g3_bi, g3_wh, g3_bh, &hbuf[1][p ^ 1][0], &hbuf[2][p][0], &hbuf[2][p ^ 1][0],
                  p_hb + (2 * 2 + (p ^ 1)) * NCOND, gil, ghl, part, rank, tid, cluster);

        // ---- out layer: 256 -> 40, this CTA's 20 outputs; 5 groups x 64 K-splits
        const float* h3n = &hbuf[2][p ^ 1][0];
        if (tid < 320) {
            int g = tid % 5, ks = tid / 5;
            const float* Wp = out_w + 20 * rank + 4 * g;
            float4 a = make_float4(0.f, 0.f, 0.f, 0.f);
            int k0 = ks * 4;
#pragma unroll
            for (int k = k0; k < k0 + 4; k++) {
                float  xk = h3n[k];
                float4 w  = *(const float4*)(Wp + (size_t)k * NSUB);
                a.x = fmaf(w.x, xk, a.x); a.y = fmaf(w.y, xk, a.y);
                a.z = fmaf(w.z, xk, a.z); a.w = fmaf(w.w, xk, a.w);
            }
            part[tid] = a;
        }
        __syncthreads();
        if (tid < 40) {
            int g = tid % 5, t = tid / 5;
            float4 r = part[(t * 8) * 5 + g];
#pragma unroll
            for (int i = 1; i < 8; i++) f4add(r, part[(t * 8 + i) * 5 + g]);
            red2[tid] = r;
        }
        __syncthreads();
        if (tid < 5) {
            float4 r = red2[tid];
#pragma unroll
            for (int t = 1; t < 8; t++) f4add(r, red2[t * 5 + tid]);
            float4 bb = *(const float4*)(out_b + 20 * rank + 4 * tid);
            float v0 = tanhf(r.x + bb.x), v1 = tanhf(r.y + bb.y);
            float v2 = tanhf(r.z + bb.z), v3 = tanhf(r.w + bb.w);
            int c = 20 * rank + 4 * tid;
            float* sp = sig + (size_t)s * NSUB + c;
            sp[0] = v0; sp[1] = v1; sp[2] = v2; sp[3] = v3;
            x_in[256 + c] = v0; x_in[256 + c + 1] = v1;
            x_in[256 + c + 2] = v2; x_in[256 + c + 3] = v3;
            p_xin[256 + c] = v0; p_xin[256 + c + 1] = v1;
            p_xin[256 + c + 2] = v2; p_xin[256 + c + 3] = v3;
        }
        cluster.sync();
    }

    // NSTEPS even -> final states live in parity buffer 0
    if (write_h && tid < 128) {
        int c = 128 * rank + tid;
        d_h[(size_t)b * NCOND + c]               = hbuf[0][0][c];
        d_h[(size_t)(BATCH + b) * NCOND + c]     = hbuf[1][0][c];
        d_h[(size_t)(2 * BATCH + b) * NCOND + c] = hbuf[2][0][c];
    }
}

// ---------------- launch ----------------
extern "C" void kernel_launch(void* const* d_in, const int* in_sizes, int n_in,
                              void* d_out, int out_size) {
    (void)n_in; (void)in_sizes;
    const float* features = (const float*)d_in[0];
    const int*   period   = (const int*)  d_in[1];
    const float* rshift   = (const float*)d_in[3];
    const float* pembed   = (const float*)d_in[4];
    const float* fd1_w = (const float*)d_in[5],  *fd1_b = (const float*)d_in[6];
    const float* c1_w  = (const float*)d_in[7],  *c1_b  = (const float*)d_in[8];
    const float* c2_w  = (const float*)d_in[9],  *c2_b  = (const float*)d_in[10];
    const float* fd2_w = (const float*)d_in[11], *fd2_b = (const float*)d_in[12];
    const float* sd1_w = (const float*)d_in[13], *sd1_b = (const float*)d_in[14];
    const float* sd2_w = (const float*)d_in[15], *sd2_b = (const float*)d_in[16];
    const float* g1_wi = (const float*)d_in[17], *g1_bi = (const float*)d_in[18];
    const float* g1_wh = (const float*)d_in[19], *g1_bh = (const float*)d_in[20];
    const float* g2_wi = (const float*)d_in[21], *g2_bi = (const float*)d_in[22];
    const float* g2_wh = (const float*)d_in[23], *g2_bh = (const float*)d_in[24];
    const float* g3_wi = (const float*)d_in[25], *g3_bi = (const float*)d_in[26];
    const float* g3_wh = (const float*)d_in[27], *g3_bh = (const float*)d_in[28];
    const float* out_w = (const float*)d_in[29], *out_b = (const float*)d_in[30];

    float* d_sig = (float*)d_out;
    const int sig_elems = BATCH * NSTEPS * NSUB;
    int write_h = (out_size >= sig_elems + 3 * BATCH * NCOND) ? 1 : 0;
    float* d_h = d_sig + sig_elems;

    // Conditioning network
    wtrans_kernel<<<(NCOND * NCOND * 3 + 255) / 256, 256>>>(c1_w, c2_w);
    phase_kernel<<<BATCH, 256>>>(period, rshift);
    fd1_kernel<<<BATCH * T_IN, 256>>>(features, period, pembed, fd1_w, fd1_b);
    conv_kernel<<<BATCH * 102, 256>>>(c1_b, 0);
    conv_kernel<<<BATCH * 100, 256>>>(c2_b, 1);
    fd2_kernel<<<BATCH * NBF, 256>>>(fd2_w, fd2_b);

    // Autoregressive recurrence: 64 clusters of 2 CTAs (128 SMs)
    rnn_kernel<<<2 * BATCH, 768>>>(sd1_w, sd1_b, sd2_w, sd2_b,
                                   g1_wi, g1_bi, g1_wh, g1_bh,
                                   g2_wi, g2_bi, g2_wh, g2_bh,
                                   g3_wi, g3_bi, g3_wh, g3_bh,
                                   out_w, out_b, d_sig, d_h, write_h);
}